// round 1
// baseline (speedup 1.0000x reference)
#include <cuda_runtime.h>
#include <cuda_bf16.h>

#define N_NODES 100000
#define N_EDGES 1600000
#define IN_F    128
#define HEADS   8
#define OUT_F   16
#define HD      128   // HEADS*OUT_F
#define NEG_SLOPE 0.2f

// ---------------- scratch (device globals; no allocation allowed) ------------
__device__ __align__(16) float g_h  [N_NODES * HD];   // projected features
__device__ __align__(16) float g_el [N_NODES * HEADS];
__device__ __align__(16) float g_er [N_NODES * HEADS];
__device__ __align__(16) float g_sum[N_NODES * HEADS];

// ---------------- K1: h = feats @ W, el/er, out = h + bias, zero g_sum -------
// block = 256 threads (8 warps). Each warp processes 4 rows at a time.
// SMEM: W[128*128] | frow[8 warps][4 rows][128] | al[128] | ar[128] | bb[128]
#define K1_BLOCK 256
#define K1_WARPS (K1_BLOCK / 32)
#define K1_SMEM  (128*128*4 + K1_WARPS*4*128*4 + 3*128*4)

__global__ void __launch_bounds__(K1_BLOCK)
k_proj(const float* __restrict__ feats, const float* __restrict__ W,
       const float* __restrict__ attn_l, const float* __restrict__ attn_r,
       const float* __restrict__ bias, float* __restrict__ out)
{
    extern __shared__ float smem[];
    float* Ws   = smem;                      // 128*128
    float* frow = Ws + 128 * 128;            // K1_WARPS*4*128
    float* al   = frow + K1_WARPS * 4 * 128; // 128
    float* ar   = al + 128;                  // 128
    float* bb   = ar + 128;                  // 128

    const int tid = threadIdx.x;

    // load W (float4 coalesced)
    for (int i = tid; i < 128 * 128 / 4; i += K1_BLOCK)
        ((float4*)Ws)[i] = ((const float4*)W)[i];
    if (tid < 128) { al[tid] = attn_l[tid]; ar[tid] = attn_r[tid]; bb[tid] = bias[tid]; }

    // zero segment-sum accumulator (must happen every launch: graph replay)
    for (int i = blockIdx.x * K1_BLOCK + tid; i < N_NODES * HEADS; i += gridDim.x * K1_BLOCK)
        g_sum[i] = 0.f;
    __syncthreads();

    const int warp = tid >> 5, lane = tid & 31;
    const int gw = blockIdx.x * K1_WARPS + warp;
    const int nw = gridDim.x * K1_WARPS;
    float* fr = frow + warp * 4 * 128;
    const int head  = lane >> 2;
    const int cbase = lane * 4;
    const float4* Ws4 = (const float4*)Ws;

    // N_NODES % 4 == 0, so all groups are full
    for (int base = gw * 4; base < N_NODES; base += nw * 4) {
        // stage 4 feature rows into smem
        #pragma unroll
        for (int r = 0; r < 4; r++)
            ((float4*)(fr + r * 128))[lane] = ((const float4*)(feats + (base + r) * IN_F))[lane];
        __syncwarp();

        float4 a0 = {0,0,0,0}, a1 = {0,0,0,0}, a2 = {0,0,0,0}, a3 = {0,0,0,0};
        #pragma unroll 4
        for (int k = 0; k < 128; k++) {
            float4 w = Ws4[k * 32 + lane];
            float f0 = fr[k], f1 = fr[128 + k], f2 = fr[256 + k], f3 = fr[384 + k];
            a0.x += f0 * w.x; a0.y += f0 * w.y; a0.z += f0 * w.z; a0.w += f0 * w.w;
            a1.x += f1 * w.x; a1.y += f1 * w.y; a1.z += f1 * w.z; a1.w += f1 * w.w;
            a2.x += f2 * w.x; a2.y += f2 * w.y; a2.z += f2 * w.z; a2.w += f2 * w.w;
            a3.x += f3 * w.x; a3.y += f3 * w.y; a3.z += f3 * w.z; a3.w += f3 * w.w;
        }

        float4 accs[4] = {a0, a1, a2, a3};
        #pragma unroll
        for (int r = 0; r < 4; r++) {
            float4 a = accs[r];
            int row = base + r;
            // el / er partial dot over this lane's 4 columns, reduce across 4 lanes
            float pl = a.x * al[cbase] + a.y * al[cbase+1] + a.z * al[cbase+2] + a.w * al[cbase+3];
            float pr = a.x * ar[cbase] + a.y * ar[cbase+1] + a.z * ar[cbase+2] + a.w * ar[cbase+3];
            pl += __shfl_xor_sync(0xffffffffu, pl, 1);
            pl += __shfl_xor_sync(0xffffffffu, pl, 2);
            pr += __shfl_xor_sync(0xffffffffu, pr, 1);
            pr += __shfl_xor_sync(0xffffffffu, pr, 2);
            if ((lane & 3) == 0) {
                g_el[row * HEADS + head] = pl;
                g_er[row * HEADS + head] = pr;
            }
            // h scratch + out = h + bias (residual folded in; atomics add on top)
            ((float4*)(g_h + row * HD))[lane] = a;
            float4 ob = make_float4(a.x + bb[cbase], a.y + bb[cbase+1],
                                    a.z + bb[cbase+2], a.w + bb[cbase+3]);
            ((float4*)(out + row * HD))[lane] = ob;
        }
        __syncwarp();
    }
}

// ---------------- K2: per-edge exp(leakyrelu(el[src]+er[dst])) -> sum[dst] ---
__device__ __forceinline__ void red_v4(float* p, float x, float y, float z, float w)
{
    asm volatile("red.global.add.v4.f32 [%0], {%1,%2,%3,%4};"
                 :: "l"(p), "f"(x), "f"(y), "f"(z), "f"(w) : "memory");
}

__global__ void __launch_bounds__(256)
k_score(const int* __restrict__ src, const int* __restrict__ dst)
{
    int e = blockIdx.x * blockDim.x + threadIdx.x;
    if (e >= N_EDGES) return;
    int s = src[e], d = dst[e];
    float4 l0 = ((const float4*)g_el)[s * 2];
    float4 l1 = ((const float4*)g_el)[s * 2 + 1];
    float4 r0 = ((const float4*)g_er)[d * 2];
    float4 r1 = ((const float4*)g_er)[d * 2 + 1];
    float v[8] = { l0.x + r0.x, l0.y + r0.y, l0.z + r0.z, l0.w + r0.w,
                   l1.x + r1.x, l1.y + r1.y, l1.z + r1.z, l1.w + r1.w };
    float ex[8];
    #pragma unroll
    for (int i = 0; i < 8; i++) {
        float a = v[i];
        a = a > 0.f ? a : NEG_SLOPE * a;
        ex[i] = __expf(a);
    }
    red_v4(g_sum + d * HEADS,     ex[0], ex[1], ex[2], ex[3]);
    red_v4(g_sum + d * HEADS + 4, ex[4], ex[5], ex[6], ex[7]);
}

// ---------------- K3: warp per edge, out[dst] += alpha * h[src] --------------
__global__ void __launch_bounds__(256)
k_agg(const int* __restrict__ src, const int* __restrict__ dst, float* __restrict__ out)
{
    int gw = (blockIdx.x * blockDim.x + threadIdx.x) >> 5;
    int lane = threadIdx.x & 31;
    if (gw >= N_EDGES) return;
    int s = __ldg(src + gw), d = __ldg(dst + gw);

    float alpha = 0.f;
    if (lane < 8) {
        float a = g_el[s * HEADS + lane] + g_er[d * HEADS + lane];
        a = a > 0.f ? a : NEG_SLOPE * a;
        alpha = __expf(a) / g_sum[d * HEADS + lane];  // identical __expf as K2
    }
    // lane covers columns [4*lane, 4*lane+3] -> head = lane>>2
    float al = __shfl_sync(0xffffffffu, alpha, lane >> 2);
    float4 hv = ((const float4*)(g_h + s * HD))[lane];
    red_v4(out + d * HD + lane * 4, al * hv.x, al * hv.y, al * hv.z, al * hv.w);
}

// ---------------- launch ------------------------------------------------------
extern "C" void kernel_launch(void* const* d_in, const int* in_sizes, int n_in,
                              void* d_out, int out_size)
{
    const float* feats  = (const float*)d_in[0];
    const float* W      = (const float*)d_in[1];
    const float* attn_l = (const float*)d_in[2];
    const float* attn_r = (const float*)d_in[3];
    const float* bias   = (const float*)d_in[4];
    const int*   src    = (const int*)d_in[5];
    const int*   dst    = (const int*)d_in[6];
    float* out = (float*)d_out;

    cudaFuncSetAttribute(k_proj, cudaFuncAttributeMaxDynamicSharedMemorySize, K1_SMEM);

    k_proj<<<444, K1_BLOCK, K1_SMEM>>>(feats, W, attn_l, attn_r, bias, out);
    k_score<<<(N_EDGES + 255) / 256, 256>>>(src, dst);
    k_agg<<<(N_EDGES * 32 + 255) / 256, 256>>>(src, dst, out);
}

// round 2
// speedup vs baseline: 1.4750x; 1.4750x over previous
#include <cuda_runtime.h>
#include <cuda_bf16.h>

#define N_NODES 100000
#define N_EDGES 1600000
#define IN_F    128
#define HEADS   8
#define OUT_F   16
#define HD      128   // HEADS*OUT_F
#define NEG_SLOPE 0.2f

// ---------------- scratch (device globals; no allocation allowed) ------------
__device__ __align__(16) float g_h  [N_NODES * HD];   // projected features
__device__ __align__(16) float g_el [N_NODES * HEADS];
__device__ __align__(16) float g_er [N_NODES * HEADS];
__device__ int   g_deg   [N_NODES];
__device__ int   g_off   [N_NODES + 1];
__device__ int   g_cursor[N_NODES];
__device__ int   g_csr_src[N_EDGES];

// ---------------- K1: h = feats @ W, el/er ----------------------------------
// block = 512 threads (16 warps), 2 blocks/SM. Each warp: 4 rows per iter.
#define K1_BLOCK 512
#define K1_WARPS (K1_BLOCK / 32)
#define K1_SMEM  (128*128*4 + K1_WARPS*4*128*4 + 2*128*4)   // 99328 B

__global__ void __launch_bounds__(K1_BLOCK, 2)
k_proj(const float* __restrict__ feats, const float* __restrict__ W,
       const float* __restrict__ attn_l, const float* __restrict__ attn_r)
{
    extern __shared__ float smem[];
    float* Ws   = smem;                      // 128*128
    float* frow = Ws + 128 * 128;            // K1_WARPS*4*128
    float* al   = frow + K1_WARPS * 4 * 128; // 128
    float* ar   = al + 128;                  // 128

    const int tid = threadIdx.x;

    for (int i = tid; i < 128 * 128 / 4; i += K1_BLOCK)
        ((float4*)Ws)[i] = ((const float4*)W)[i];
    if (tid < 128) { al[tid] = attn_l[tid]; ar[tid] = attn_r[tid]; }
    __syncthreads();

    const int warp = tid >> 5, lane = tid & 31;
    const int gw = blockIdx.x * K1_WARPS + warp;
    const int nw = gridDim.x * K1_WARPS;
    float* fr = frow + warp * 4 * 128;
    const int head  = lane >> 2;
    const int cbase = lane * 4;
    const float4* Ws4 = (const float4*)Ws;

    for (int base = gw * 4; base < N_NODES; base += nw * 4) {
        #pragma unroll
        for (int r = 0; r < 4; r++)
            ((float4*)(fr + r * 128))[lane] = ((const float4*)(feats + (base + r) * IN_F))[lane];
        __syncwarp();

        float4 a0 = {0,0,0,0}, a1 = {0,0,0,0}, a2 = {0,0,0,0}, a3 = {0,0,0,0};
        #pragma unroll 2
        for (int k4 = 0; k4 < 128; k4 += 4) {
            float4 F0 = *(const float4*)(fr + k4);
            float4 F1 = *(const float4*)(fr + 128 + k4);
            float4 F2 = *(const float4*)(fr + 256 + k4);
            float4 F3 = *(const float4*)(fr + 384 + k4);
            float f0[4] = {F0.x, F0.y, F0.z, F0.w};
            float f1[4] = {F1.x, F1.y, F1.z, F1.w};
            float f2[4] = {F2.x, F2.y, F2.z, F2.w};
            float f3[4] = {F3.x, F3.y, F3.z, F3.w};
            #pragma unroll
            for (int kk = 0; kk < 4; kk++) {
                float4 w = Ws4[(k4 + kk) * 32 + lane];
                a0.x += f0[kk]*w.x; a0.y += f0[kk]*w.y; a0.z += f0[kk]*w.z; a0.w += f0[kk]*w.w;
                a1.x += f1[kk]*w.x; a1.y += f1[kk]*w.y; a1.z += f1[kk]*w.z; a1.w += f1[kk]*w.w;
                a2.x += f2[kk]*w.x; a2.y += f2[kk]*w.y; a2.z += f2[kk]*w.z; a2.w += f2[kk]*w.w;
                a3.x += f3[kk]*w.x; a3.y += f3[kk]*w.y; a3.z += f3[kk]*w.z; a3.w += f3[kk]*w.w;
            }
        }

        float4 accs[4] = {a0, a1, a2, a3};
        #pragma unroll
        for (int r = 0; r < 4; r++) {
            float4 a = accs[r];
            int row = base + r;
            float pl = a.x * al[cbase] + a.y * al[cbase+1] + a.z * al[cbase+2] + a.w * al[cbase+3];
            float pr = a.x * ar[cbase] + a.y * ar[cbase+1] + a.z * ar[cbase+2] + a.w * ar[cbase+3];
            pl += __shfl_xor_sync(0xffffffffu, pl, 1);
            pl += __shfl_xor_sync(0xffffffffu, pl, 2);
            pr += __shfl_xor_sync(0xffffffffu, pr, 1);
            pr += __shfl_xor_sync(0xffffffffu, pr, 2);
            if ((lane & 3) == 0) {
                g_el[row * HEADS + head] = pl;
                g_er[row * HEADS + head] = pr;
            }
            ((float4*)(g_h + row * HD))[lane] = a;
        }
        __syncwarp();
    }
}

// ---------------- CSR build ---------------------------------------------------
__global__ void __launch_bounds__(512)
k_zero()
{
    for (int i = blockIdx.x * 512 + threadIdx.x; i < N_NODES; i += gridDim.x * 512)
        g_deg[i] = 0;
}

__global__ void __launch_bounds__(256)
k_hist(const int* __restrict__ dst)
{
    int e = blockIdx.x * 256 + threadIdx.x;
    if (e < N_EDGES) atomicAdd(&g_deg[dst[e]], 1);
}

// single-block exclusive scan over g_deg -> g_off, g_cursor
__global__ void __launch_bounds__(1024)
k_scan()
{
    __shared__ int wsum[32];
    __shared__ int carry_s;
    const int tid = threadIdx.x, lane = tid & 31, warp = tid >> 5;
    if (tid == 0) carry_s = 0;
    __syncthreads();

    for (int base = 0; base < N_NODES; base += 1024) {
        int i = base + tid;
        int v = (i < N_NODES) ? g_deg[i] : 0;
        int x = v;
        #pragma unroll
        for (int o = 1; o < 32; o <<= 1) {
            int y = __shfl_up_sync(0xffffffffu, x, o);
            if (lane >= o) x += y;
        }
        if (lane == 31) wsum[warp] = x;
        __syncthreads();
        if (warp == 0) {
            int s = wsum[lane];
            #pragma unroll
            for (int o = 1; o < 32; o <<= 1) {
                int y = __shfl_up_sync(0xffffffffu, s, o);
                if (lane >= o) s += y;
            }
            wsum[lane] = s;  // inclusive across warps
        }
        __syncthreads();
        int warpoff = (warp == 0) ? 0 : wsum[warp - 1];
        int excl = carry_s + warpoff + x - v;
        if (i < N_NODES) { g_off[i] = excl; g_cursor[i] = excl; }
        int blocktotal = wsum[31];
        __syncthreads();
        if (tid == 0) carry_s += blocktotal;
        __syncthreads();
    }
    if (tid == 0) g_off[N_NODES] = carry_s;
}

__global__ void __launch_bounds__(256)
k_scatter(const int* __restrict__ src, const int* __restrict__ dst)
{
    int e = blockIdx.x * 256 + threadIdx.x;
    if (e >= N_EDGES) return;
    int d = dst[e];
    int pos = atomicAdd(&g_cursor[d], 1);
    g_csr_src[pos] = src[e];
}

// ---------------- K3: warp per dst node, atomic-free aggregation -------------
// acc_h[d] = sum_e exp(leaky(el[s]+er[d]))*h[s];  out = acc/sum + h[d] + bias
__global__ void __launch_bounds__(256)
k_agg(const float* __restrict__ bias, float* __restrict__ out)
{
    int gw = (blockIdx.x * 256 + threadIdx.x) >> 5;
    int lane = threadIdx.x & 31;
    if (gw >= N_NODES) return;
    const int d = gw;
    const int head = lane >> 2;

    int start = g_off[d], end = g_off[d + 1];
    float erd = (lane < 8) ? g_er[d * HEADS + lane] : 0.f;
    float sum = 0.f;
    float4 acc = {0.f, 0.f, 0.f, 0.f};

    for (int base = start; base < end; base += 32) {
        int idx = base + lane;
        int myS = (idx < end) ? g_csr_src[idx] : 0;
        int cnt = min(32, end - base);
        #pragma unroll 4
        for (int t = 0; t < cnt; t++) {
            int s = __shfl_sync(0xffffffffu, myS, t);
            float ex = 0.f;
            if (lane < 8) {
                float a = g_el[s * HEADS + lane] + erd;
                a = a > 0.f ? a : NEG_SLOPE * a;
                ex = __expf(a);
                sum += ex;
            }
            float exh = __shfl_sync(0xffffffffu, ex, head);
            float4 hv = ((const float4*)(g_h + s * HD))[lane];
            acc.x += exh * hv.x; acc.y += exh * hv.y;
            acc.z += exh * hv.z; acc.w += exh * hv.w;
        }
    }

    float sumh = __shfl_sync(0xffffffffu, sum, head);
    float inv = (end > start) ? 1.f / sumh : 0.f;   // zero in-degree guard
    float4 hd = ((const float4*)(g_h + d * HD))[lane];
    float4 b  = ((const float4*)bias)[lane];
    float4 o;
    o.x = acc.x * inv + hd.x + b.x;
    o.y = acc.y * inv + hd.y + b.y;
    o.z = acc.z * inv + hd.z + b.z;
    o.w = acc.w * inv + hd.w + b.w;
    ((float4*)(out + d * HD))[lane] = o;
}

// ---------------- launch ------------------------------------------------------
extern "C" void kernel_launch(void* const* d_in, const int* in_sizes, int n_in,
                              void* d_out, int out_size)
{
    const float* feats  = (const float*)d_in[0];
    const float* W      = (const float*)d_in[1];
    const float* attn_l = (const float*)d_in[2];
    const float* attn_r = (const float*)d_in[3];
    const float* bias   = (const float*)d_in[4];
    const int*   src    = (const int*)d_in[5];
    const int*   dst    = (const int*)d_in[6];
    float* out = (float*)d_out;

    cudaFuncSetAttribute(k_proj, cudaFuncAttributeMaxDynamicSharedMemorySize, K1_SMEM);

    k_zero<<<64, 512>>>();
    k_hist<<<(N_EDGES + 255) / 256, 256>>>(dst);
    k_scan<<<1, 1024>>>();
    k_scatter<<<(N_EDGES + 255) / 256, 256>>>(src, dst);
    k_proj<<<296, K1_BLOCK, K1_SMEM>>>(feats, W, attn_l, attn_r);
    k_agg<<<(N_NODES * 32 + 255) / 256, 256>>>(bias, out);
}

// round 3
// speedup vs baseline: 2.0155x; 1.3664x over previous
#include <cuda_runtime.h>
#include <cuda_bf16.h>

#define N_NODES 100000
#define N_EDGES 1600000
#define IN_F    128
#define HEADS   8
#define OUT_F   16
#define HD      128   // HEADS*OUT_F
#define NEG_SLOPE 0.2f

// ---------------- scratch (device globals; no allocation allowed) ------------
__device__ __align__(16) float g_h  [N_NODES * HD];   // projected features
__device__ __align__(16) float g_el [N_NODES * HEADS];
__device__ __align__(16) float g_er [N_NODES * HEADS];
__device__ int   g_deg   [N_NODES];
__device__ int   g_off   [N_NODES + 1];
__device__ int   g_cursor[N_NODES];
__device__ int   g_csr_src[N_EDGES];

// ---------------- K1: h = feats @ W, el/er ----------------------------------
#define K1_BLOCK 512
#define K1_WARPS (K1_BLOCK / 32)
#define K1_SMEM  (128*128*4 + K1_WARPS*4*128*4 + 2*128*4)   // 99328 B

__global__ void __launch_bounds__(K1_BLOCK, 2)
k_proj(const float* __restrict__ feats, const float* __restrict__ W,
       const float* __restrict__ attn_l, const float* __restrict__ attn_r)
{
    extern __shared__ float smem[];
    float* Ws   = smem;                      // 128*128
    float* frow = Ws + 128 * 128;            // K1_WARPS*4*128
    float* al   = frow + K1_WARPS * 4 * 128; // 128
    float* ar   = al + 128;                  // 128

    const int tid = threadIdx.x;

    for (int i = tid; i < 128 * 128 / 4; i += K1_BLOCK)
        ((float4*)Ws)[i] = ((const float4*)W)[i];
    if (tid < 128) { al[tid] = attn_l[tid]; ar[tid] = attn_r[tid]; }
    __syncthreads();

    const int warp = tid >> 5, lane = tid & 31;
    const int gw = blockIdx.x * K1_WARPS + warp;
    const int nw = gridDim.x * K1_WARPS;
    float* fr = frow + warp * 4 * 128;
    const int head  = lane >> 2;
    const int cbase = lane * 4;
    const float4* Ws4 = (const float4*)Ws;

    for (int base = gw * 4; base < N_NODES; base += nw * 4) {
        #pragma unroll
        for (int r = 0; r < 4; r++)
            ((float4*)(fr + r * 128))[lane] = ((const float4*)(feats + (base + r) * IN_F))[lane];
        __syncwarp();

        float4 a0 = {0,0,0,0}, a1 = {0,0,0,0}, a2 = {0,0,0,0}, a3 = {0,0,0,0};
        #pragma unroll 2
        for (int k4 = 0; k4 < 128; k4 += 4) {
            float4 F0 = *(const float4*)(fr + k4);
            float4 F1 = *(const float4*)(fr + 128 + k4);
            float4 F2 = *(const float4*)(fr + 256 + k4);
            float4 F3 = *(const float4*)(fr + 384 + k4);
            float f0[4] = {F0.x, F0.y, F0.z, F0.w};
            float f1[4] = {F1.x, F1.y, F1.z, F1.w};
            float f2[4] = {F2.x, F2.y, F2.z, F2.w};
            float f3[4] = {F3.x, F3.y, F3.z, F3.w};
            #pragma unroll
            for (int kk = 0; kk < 4; kk++) {
                float4 w = Ws4[(k4 + kk) * 32 + lane];
                a0.x += f0[kk]*w.x; a0.y += f0[kk]*w.y; a0.z += f0[kk]*w.z; a0.w += f0[kk]*w.w;
                a1.x += f1[kk]*w.x; a1.y += f1[kk]*w.y; a1.z += f1[kk]*w.z; a1.w += f1[kk]*w.w;
                a2.x += f2[kk]*w.x; a2.y += f2[kk]*w.y; a2.z += f2[kk]*w.z; a2.w += f2[kk]*w.w;
                a3.x += f3[kk]*w.x; a3.y += f3[kk]*w.y; a3.z += f3[kk]*w.z; a3.w += f3[kk]*w.w;
            }
        }

        float4 accs[4] = {a0, a1, a2, a3};
        #pragma unroll
        for (int r = 0; r < 4; r++) {
            float4 a = accs[r];
            int row = base + r;
            float pl = a.x * al[cbase] + a.y * al[cbase+1] + a.z * al[cbase+2] + a.w * al[cbase+3];
            float pr = a.x * ar[cbase] + a.y * ar[cbase+1] + a.z * ar[cbase+2] + a.w * ar[cbase+3];
            pl += __shfl_xor_sync(0xffffffffu, pl, 1);
            pl += __shfl_xor_sync(0xffffffffu, pl, 2);
            pr += __shfl_xor_sync(0xffffffffu, pr, 1);
            pr += __shfl_xor_sync(0xffffffffu, pr, 2);
            if ((lane & 3) == 0) {
                g_el[row * HEADS + head] = pl;
                g_er[row * HEADS + head] = pr;
            }
            ((float4*)(g_h + row * HD))[lane] = a;
        }
        __syncwarp();
    }
}

// ---------------- CSR build ---------------------------------------------------
__global__ void __launch_bounds__(512)
k_zero()
{
    for (int i = blockIdx.x * 512 + threadIdx.x; i < N_NODES; i += gridDim.x * 512)
        g_deg[i] = 0;
}

__global__ void __launch_bounds__(256)
k_hist(const int* __restrict__ dst)
{
    int e = blockIdx.x * 256 + threadIdx.x;
    if (e < N_EDGES) atomicAdd(&g_deg[dst[e]], 1);
}

// single-block exclusive scan over g_deg -> g_off, g_cursor
__global__ void __launch_bounds__(1024)
k_scan()
{
    __shared__ int wsum[32];
    __shared__ int carry_s;
    const int tid = threadIdx.x, lane = tid & 31, warp = tid >> 5;
    if (tid == 0) carry_s = 0;
    __syncthreads();

    for (int base = 0; base < N_NODES; base += 1024) {
        int i = base + tid;
        int v = (i < N_NODES) ? g_deg[i] : 0;
        int x = v;
        #pragma unroll
        for (int o = 1; o < 32; o <<= 1) {
            int y = __shfl_up_sync(0xffffffffu, x, o);
            if (lane >= o) x += y;
        }
        if (lane == 31) wsum[warp] = x;
        __syncthreads();
        if (warp == 0) {
            int s = wsum[lane];
            #pragma unroll
            for (int o = 1; o < 32; o <<= 1) {
                int y = __shfl_up_sync(0xffffffffu, s, o);
                if (lane >= o) s += y;
            }
            wsum[lane] = s;  // inclusive across warps
        }
        __syncthreads();
        int warpoff = (warp == 0) ? 0 : wsum[warp - 1];
        int excl = carry_s + warpoff + x - v;
        if (i < N_NODES) { g_off[i] = excl; g_cursor[i] = excl; }
        int blocktotal = wsum[31];
        __syncthreads();
        if (tid == 0) carry_s += blocktotal;
        __syncthreads();
    }
    if (tid == 0) g_off[N_NODES] = carry_s;
}

__global__ void __launch_bounds__(256)
k_scatter(const int* __restrict__ src, const int* __restrict__ dst)
{
    int e = blockIdx.x * 256 + threadIdx.x;
    if (e >= N_EDGES) return;
    int d = dst[e];
    int pos = atomicAdd(&g_cursor[d], 1);
    g_csr_src[pos] = src[e];
}

// ---------------- K3: warp per dst node, atomic-free aggregation -------------
__global__ void __launch_bounds__(256)
k_agg(const float* __restrict__ bias, float* __restrict__ out)
{
    int gw = (blockIdx.x * 256 + threadIdx.x) >> 5;
    int lane = threadIdx.x & 31;
    if (gw >= N_NODES) return;
    const int d = gw;
    const int head = lane >> 2;

    int start = g_off[d], end = g_off[d + 1];
    float erd = (lane < 8) ? g_er[d * HEADS + lane] : 0.f;
    float sum = 0.f;
    float4 acc = {0.f, 0.f, 0.f, 0.f};

    for (int base = start; base < end; base += 32) {
        int idx = base + lane;
        int myS = (idx < end) ? g_csr_src[idx] : 0;
        int cnt = min(32, end - base);
        #pragma unroll 4
        for (int t = 0; t < cnt; t++) {
            int s = __shfl_sync(0xffffffffu, myS, t);
            float ex = 0.f;
            if (lane < 8) {
                float a = g_el[s * HEADS + lane] + erd;
                a = a > 0.f ? a : NEG_SLOPE * a;
                ex = __expf(a);
                sum += ex;
            }
            float exh = __shfl_sync(0xffffffffu, ex, head);
            float4 hv = ((const float4*)(g_h + s * HD))[lane];
            acc.x += exh * hv.x; acc.y += exh * hv.y;
            acc.z += exh * hv.z; acc.w += exh * hv.w;
        }
    }

    float sumh = __shfl_sync(0xffffffffu, sum, head);
    float inv = (end > start) ? 1.f / sumh : 0.f;   // zero in-degree guard
    float4 hd = ((const float4*)(g_h + d * HD))[lane];
    float4 b  = ((const float4*)bias)[lane];
    float4 o;
    o.x = acc.x * inv + hd.x + b.x;
    o.y = acc.y * inv + hd.y + b.y;
    o.z = acc.z * inv + hd.z + b.z;
    o.w = acc.w * inv + hd.w + b.w;
    ((float4*)(out + d * HD))[lane] = o;
}

// ---------------- launch ------------------------------------------------------
// Fork/join: CSR build chain runs on a side stream concurrently with k_proj,
// joined before k_agg. Streams/events are created per call and intentionally
// not destroyed: kernel_launch is invoked only a handful of times (correctness
// + capture), and destroying a stream that participates in an active capture
// would invalidate the graph.
extern "C" void kernel_launch(void* const* d_in, const int* in_sizes, int n_in,
                              void* d_out, int out_size)
{
    const float* feats  = (const float*)d_in[0];
    const float* W      = (const float*)d_in[1];
    const float* attn_l = (const float*)d_in[2];
    const float* attn_r = (const float*)d_in[3];
    const float* bias   = (const float*)d_in[4];
    const int*   src    = (const int*)d_in[5];
    const int*   dst    = (const int*)d_in[6];
    float* out = (float*)d_out;

    cudaFuncSetAttribute(k_proj, cudaFuncAttributeMaxDynamicSharedMemorySize, K1_SMEM);

    cudaStream_t side;
    cudaEvent_t ev_fork, ev_join;
    cudaStreamCreateWithFlags(&side, cudaStreamNonBlocking);
    cudaEventCreateWithFlags(&ev_fork, cudaEventDisableTiming);
    cudaEventCreateWithFlags(&ev_join, cudaEventDisableTiming);

    // fork from the (captured) default stream
    cudaEventRecord(ev_fork, 0);
    cudaStreamWaitEvent(side, ev_fork, 0);

    // CSR build chain on side stream (independent of projection)
    k_zero<<<64, 512, 0, side>>>();
    k_hist<<<(N_EDGES + 255) / 256, 256, 0, side>>>(dst);
    k_scan<<<1, 1024, 0, side>>>();
    k_scatter<<<(N_EDGES + 255) / 256, 256, 0, side>>>(src, dst);
    cudaEventRecord(ev_join, side);

    // projection on the main (captured) stream, concurrent with CSR build
    k_proj<<<296, K1_BLOCK, K1_SMEM>>>(feats, W, attn_l, attn_r);

    // join, then aggregate
    cudaStreamWaitEvent(0, ev_join, 0);
    k_agg<<<(N_NODES * 32 + 255) / 256, 256>>>(bias, out);
}